// round 16
// baseline (speedup 1.0000x reference)
#include <cuda_runtime.h>
#include <cuda_bf16.h>
#include <cuda_fp16.h>
#include <cstdint>
#include <math.h>

// Problem constants (fixed by the dataset)
#define NN   100000
#define EE   1600000
#define F_IN 128
#define HID  256
#define NC   64
#define NBLK ((NN + 255) / 256)   // 391

// ---------------------------------------------------------------------------
// Scratch (static __device__ arrays — no allocation allowed)
// ---------------------------------------------------------------------------
__device__ float g_deg[NN];
__device__ float g_dinv[NN];
__device__ int   g_wptr[NN];
__device__ int   g_rowptr[NN + 1];
__device__ int   g_aggflag[NBLK];   // look-back scan: aggregate published?
__device__ int   g_aggval[NBLK];
__device__ int   g_csrc[EE];
__device__ float g_cnorm[EE];
__device__ __align__(16) __half g_x16[(size_t)NN * F_IN];    // x in fp16
__device__ __align__(16) __half g_xagg[(size_t)NN * F_IN];   // agg(x) fp16
__device__ __align__(16) __half g_t16a[(size_t)NN * HID];    // fp16 ping
__device__ __align__(16) __half g_t16b[(size_t)NN * HID];    // fp16 pong
__device__ __align__(16) __half g_w0h[HID * F_IN];           // W^T fp16
__device__ __align__(16) __half g_w1h[HID * HID];
__device__ __align__(16) __half g_w2h[NC * HID];

// ---------------------------------------------------------------------------
// PTX helpers (portable sm_80+; works on generic sm_103 target)
// ---------------------------------------------------------------------------
__device__ __forceinline__ uint32_t smem_u32(const void* p) {
    uint32_t a;
    asm("{ .reg .u64 t; cvta.to.shared.u64 t, %1; cvt.u32.u64 %0, t; }"
        : "=r"(a) : "l"(p));
    return a;
}

#define LDSM4(r, addr) \
    asm volatile("ldmatrix.sync.aligned.m8n8.x4.shared.b16 {%0,%1,%2,%3}, [%4];" \
        : "=r"((r)[0]), "=r"((r)[1]), "=r"((r)[2]), "=r"((r)[3]) : "r"(addr))

#define MMA_F16(c, a, b0, b1) \
    asm volatile("mma.sync.aligned.m16n8k16.row.col.f32.f16.f16.f32 " \
        "{%0,%1,%2,%3}, {%4,%5,%6,%7}, {%8,%9}, {%0,%1,%2,%3};" \
        : "+f"((c)[0]), "+f"((c)[1]), "+f"((c)[2]), "+f"((c)[3]) \
        : "r"((a)[0]), "r"((a)[1]), "r"((a)[2]), "r"((a)[3]), "r"(b0), "r"(b1))

#define CP16(dst, src, sz) \
    asm volatile("cp.async.cg.shared.global [%0], [%1], 16, %2;" \
        :: "r"(dst), "l"(src), "r"(sz) : "memory")
#define CP_COMMIT() asm volatile("cp.async.commit_group;" ::: "memory")
template <int N>
__device__ __forceinline__ void cp_wait() {
    asm volatile("cp.async.wait_group %0;" :: "n"(N) : "memory");
}

// ---------------------------------------------------------------------------
// Preprocessing kernels
// ---------------------------------------------------------------------------
__global__ void k_init()
{
    int i = blockIdx.x * blockDim.x + threadIdx.x;
    if (i < NN) { g_deg[i] = 1.0f; g_wptr[i] = 0; }
    if (i < NBLK) g_aggflag[i] = 0;    // reset look-back flags each replay
}

// 2 edges per thread (int2/float2 vector loads)
__global__ void k_deg_count(const int* __restrict__ dst, const float* __restrict__ w)
{
    int i = blockIdx.x * blockDim.x + threadIdx.x;
    if (i < EE / 2) {
        int2   d2 = ((const int2*)dst)[i];
        float2 w2 = ((const float2*)w)[i];
        atomicAdd(&g_deg[d2.x], w2.x);
        atomicAdd(&g_wptr[d2.x], 1);
        atomicAdd(&g_deg[d2.y], w2.y);
        atomicAdd(&g_wptr[d2.y], 1);
    }
}

// Fused: dinv + block scan + decoupled-aggregate look-back -> rowptr.
// All NBLK=391 blocks are co-resident (256 thr, low regs), so spinning on
// predecessor aggregates is deadlock-free.
__global__ void k_scan_fused()
{
    __shared__ int sh[256];
    __shared__ int sh2[256];
    const int b = blockIdx.x, t = threadIdx.x;
    const int i = b * 256 + t;
    const int v = (i < NN) ? g_wptr[i] : 0;
    if (i < NN) g_dinv[i] = rsqrtf(g_deg[i]);

    // inclusive block scan
    sh[t] = v;
    __syncthreads();
    #pragma unroll
    for (int o = 1; o < 256; o <<= 1) {
        int a = (t >= o) ? sh[t - o] : 0;
        __syncthreads();
        sh[t] += a;
        __syncthreads();
    }

    // publish this block's aggregate
    if (t == 255) {
        g_aggval[b] = sh[255];
        __threadfence();
        atomicExch(&g_aggflag[b], 1);
    }

    // look-back: cooperatively sum predecessor aggregates
    int pre = 0;
    for (int j = t; j < b; j += 256) {
        while (atomicAdd(&g_aggflag[j], 0) == 0) {}
        pre += g_aggval[j];
    }
    sh2[t] = pre;
    __syncthreads();
    #pragma unroll
    for (int o = 128; o > 0; o >>= 1) {
        if (t < o) sh2[t] += sh2[t + o];
        __syncthreads();
    }
    const int blkoff = sh2[0];

    if (i < NN) {
        int off = blkoff + sh[t] - v;   // exclusive prefix
        g_rowptr[i] = off;
        g_wptr[i]   = off;              // write cursor for fill
    }
    if (i == NN - 1) g_rowptr[NN] = EE;
}

// 2 edges per thread (vector loads)
__global__ void k_fill(const int* __restrict__ src, const int* __restrict__ dst,
                       const float* __restrict__ w)
{
    int i = blockIdx.x * blockDim.x + threadIdx.x;
    if (i < EE / 2) {
        int2   s2 = ((const int2*)src)[i];
        int2   d2 = ((const int2*)dst)[i];
        float2 w2 = ((const float2*)w)[i];
        float nm0 = g_dinv[s2.x] * w2.x * g_dinv[d2.x];
        int slot0 = atomicAdd(&g_wptr[d2.x], 1);
        g_csrc[slot0]  = s2.x;
        g_cnorm[slot0] = nm0;
        float nm1 = g_dinv[s2.y] * w2.y * g_dinv[d2.y];
        int slot1 = atomicAdd(&g_wptr[d2.y], 1);
        g_csrc[slot1]  = s2.y;
        g_cnorm[slot1] = nm1;
    }
}

// Fused operand prep: x -> fp16 (4 floats/thread) AND all three weight
// transposes (thread i also handles weight element i when in range).
#define WTOT (F_IN * HID + HID * HID + HID * NC)
__global__ void k_prep(const float* __restrict__ x, __half* __restrict__ xh,
                       const float* __restrict__ W0, const float* __restrict__ W1,
                       const float* __restrict__ W2)
{
    int i = blockIdx.x * blockDim.x + threadIdx.x;
    if (i < NN * F_IN / 4) {
        float4 v = ((const float4*)x)[i];
        ((__half2*)xh)[2 * i]     = __floats2half2_rn(v.x, v.y);
        ((__half2*)xh)[2 * i + 1] = __floats2half2_rn(v.z, v.w);
    }
    if (i < WTOT) {
        const float* W; __half* wt; int K, Ncols, j;
        if (i < F_IN * HID)                  { W = W0; wt = g_w0h; K = F_IN; Ncols = HID; j = i; }
        else if (i < F_IN * HID + HID * HID) { W = W1; wt = g_w1h; K = HID;  Ncols = HID; j = i - F_IN * HID; }
        else                                 { W = W2; wt = g_w2h; K = HID;  Ncols = NC;  j = i - F_IN * HID - HID * HID; }
        int n = j / K, k = j % K;
        wt[j] = __float2half(W[k * Ncols + n]);
    }
}

// ---------------------------------------------------------------------------
// FP16 HMMA GEMM, cp.async double-buffered (round-15 proven).
//   C[M, ldc] = A[M, KT] @ Bt[Ncols, KT]^T ; A,Bt fp16, fp32 accumulate.
//   BM=128, BN=64, BK=32, 256 threads (warps 4m x 2n, warp tile 32x32).
//   Smem: 2 stages x 12288 B (static 24 KB), 64 B rows, XOR-16B swizzle.
//   EPI=0: plain fp16 store. EPI=1: bias+relu+fp16 store.
// ---------------------------------------------------------------------------
template <int EPI>
__global__ void __launch_bounds__(256)
gemm_h(int M, int KT,
       const __half* __restrict__ A, const __half* __restrict__ B,
       __half* __restrict__ Ch, const float* __restrict__ bias, int ldc)
{
    constexpr int STG = 12288;          // A 128*64B + B 64*64B
    constexpr int OFF_A = 0, OFF_B = 8192;

    __shared__ __align__(16) char sm[2 * STG];
    const uint32_t smb = smem_u32(sm);

    const int tid  = threadIdx.x;
    const int lane = tid & 31, wid = tid >> 5;
    const int wm = wid & 3;             // 0..3  (m)
    const int wn = wid >> 2;            // 0..1  (n)
    const int rowBase = blockIdx.y * 128;
    const int colBase = blockIdx.x * 64;

    float c[2][4][4];
    #pragma unroll
    for (int mi = 0; mi < 2; mi++)
        #pragma unroll
        for (int nf = 0; nf < 4; nf++)
            #pragma unroll
            for (int j = 0; j < 4; j++) c[mi][nf][j] = 0.f;

    // ldmatrix per-lane rows + swizzle keys
    const int lane15 = lane & 15;
    int  rA[2], rB[2];
    rA[0] = wm * 32 + lane15;  rA[1] = rA[0] + 16;
    rB[0] = wn * 32 + lane15;  rB[1] = rB[0] + 16;
    const int swA0 = (rA[0] >> 1) & 3, swA1 = (rA[1] >> 1) & 3;
    const int swB0 = (rB[0] >> 1) & 3, swB1 = (rB[1] >> 1) & 3;
    const int ccB  = lane >> 4;

    const int nchunk = KT >> 5;

    // ---- tile loader (cp.async): rows of 32 fp16 = 4 x 16B chunks, swizzled
    auto ld_tiles = [&](int st, int ch) {
        const uint32_t sb = smb + st * STG;
        const int k0 = ch * 32;
        #pragma unroll
        for (int i = tid; i < 512; i += 256) {      // A: 128 rows x 4 chunks
            int row = i >> 2, cc = i & 3;
            int gr  = rowBase + row;
            uint32_t sz = (gr < M) ? 16u : 0u;
            int gra = (gr < M) ? gr : (M - 1);
            size_t go = (size_t)gra * KT + k0 + cc * 8;
            uint32_t d = row * 64 + ((cc ^ ((row >> 1) & 3)) << 4);
            CP16(sb + OFF_A + d, (const char*)(A + go), sz);
        }
        {                                            // B: 64 rows x 4 chunks
            int row = tid >> 2, cc = tid & 3;
            size_t go = (size_t)(colBase + row) * KT + k0 + cc * 8;
            uint32_t d = row * 64 + ((cc ^ ((row >> 1) & 3)) << 4);
            CP16(sb + OFF_B + d, (const char*)(B + go), 16u);
        }
    };

    ld_tiles(0, 0);
    CP_COMMIT();

    for (int ch = 0; ch < nchunk; ch++) {
        if (ch + 1 < nchunk) { ld_tiles((ch + 1) & 1, ch + 1); CP_COMMIT(); }
        if (ch + 1 < nchunk) cp_wait<1>(); else cp_wait<0>();
        __syncthreads();

        const uint32_t sb = smb + (ch & 1) * STG;
        #pragma unroll
        for (int ks = 0; ks < 2; ks++) {
            const int cc = ccB + 2 * ks;
            uint32_t a[2][4], b[2][4];
            LDSM4(a[0], sb + OFF_A + rA[0] * 64 + ((cc ^ swA0) << 4));
            LDSM4(a[1], sb + OFF_A + rA[1] * 64 + ((cc ^ swA1) << 4));
            LDSM4(b[0], sb + OFF_B + rB[0] * 64 + ((cc ^ swB0) << 4));
            LDSM4(b[1], sb + OFF_B + rB[1] * 64 + ((cc ^ swB1) << 4));
            #pragma unroll
            for (int mi = 0; mi < 2; mi++)
                #pragma unroll
                for (int nf = 0; nf < 4; nf++) {
                    const int p = nf >> 1, s = nf & 1;
                    MMA_F16(c[mi][nf], a[mi], b[p][s], b[p][s + 2]);
                }
        }
        __syncthreads();
    }

    // ---- epilogue: fp16 store (optionally bias+relu) ----
    #pragma unroll
    for (int mi = 0; mi < 2; mi++) {
        const int r0 = rowBase + wm * 32 + mi * 16 + (lane >> 2);
        #pragma unroll
        for (int nf = 0; nf < 4; nf++) {
            const int col = colBase + wn * 32 + nf * 8 + (lane & 3) * 2;
            float bx = 0.f, by = 0.f;
            if (EPI == 1) { bx = __ldg(bias + col); by = __ldg(bias + col + 1); }
            #pragma unroll
            for (int h = 0; h < 2; h++) {
                const int r = r0 + 8 * h;
                if (r >= M) continue;
                float v0 = c[mi][nf][2 * h + 0];
                float v1 = c[mi][nf][2 * h + 1];
                if (EPI == 1) {
                    v0 = fmaxf(v0 + bx, 0.f);
                    v1 = fmaxf(v1 + by, 0.f);
                }
                *(__half2*)(Ch + (size_t)r * ldc + col) = __floats2half2_rn(v0, v1);
            }
        }
    }
}

// ---------------------------------------------------------------------------
// Gather aggregation over fp16 rows (half8 = 16B per lane, 4-edge unroll,
// 2 accumulator sets):
//   r = sum_e norm_e * t[src_e] + dinv[i]^2 * t[i] (+ bias) ; (relu)
//   Accumulate fp32. EMIT_H: store fp16 (GEMM input); else fp32.
// ---------------------------------------------------------------------------
__device__ __forceinline__ void h8_fma(float* acc, uint4 v, float w)
{
    float2 f0 = __half22float2(*(const __half2*)&v.x);
    float2 f1 = __half22float2(*((const __half2*)&v.x + 1));
    float2 f2 = __half22float2(*(const __half2*)&v.z);
    float2 f3 = __half22float2(*((const __half2*)&v.z + 1));
    acc[0] += w * f0.x; acc[1] += w * f0.y;
    acc[2] += w * f1.x; acc[3] += w * f1.y;
    acc[4] += w * f2.x; acc[5] += w * f2.y;
    acc[6] += w * f3.x; acc[7] += w * f3.y;
}

template <int D, bool RELU, bool EMIT_H, bool BIAS>
__global__ void agg_h(const __half* __restrict__ t,
                      __half* __restrict__ outh, float* __restrict__ outf,
                      const float* __restrict__ bias, int n)
{
    constexpr int L = D / 8;        // lanes per node (8 dims per lane)
    constexpr int G = 256 / L;      // nodes per block
    const int lane = threadIdx.x % L;
    const int sub  = threadIdx.x / L;
    const int node = blockIdx.x * G + sub;
    if (node >= n) return;

    float a0[8] = {}, a1[8] = {};
    if (BIAS) {
        float4 b0 = ((const float4*)bias)[2 * lane];
        float4 b1 = ((const float4*)bias)[2 * lane + 1];
        a0[0] = b0.x; a0[1] = b0.y; a0[2] = b0.z; a0[3] = b0.w;
        a0[4] = b1.x; a0[5] = b1.y; a0[6] = b1.z; a0[7] = b1.w;
    }
    const float di = g_dinv[node];
    {   // self loop: dinv^2 * t[node]
        uint4 sv = __ldg((const uint4*)(t + (size_t)node * D) + lane);
        h8_fma(a0, sv, di * di);
    }

    int e   = g_rowptr[node];
    int end = g_rowptr[node + 1];
    for (; e + 3 < end; e += 4) {
        int   s0 = g_csrc[e],     s1 = g_csrc[e + 1];
        int   s2 = g_csrc[e + 2], s3 = g_csrc[e + 3];
        float w0 = g_cnorm[e],     w1 = g_cnorm[e + 1];
        float w2 = g_cnorm[e + 2], w3 = g_cnorm[e + 3];
        uint4 v0 = __ldg((const uint4*)(t + (size_t)s0 * D) + lane);
        uint4 v1 = __ldg((const uint4*)(t + (size_t)s1 * D) + lane);
        uint4 v2 = __ldg((const uint4*)(t + (size_t)s2 * D) + lane);
        uint4 v3 = __ldg((const uint4*)(t + (size_t)s3 * D) + lane);
        h8_fma(a0, v0, w0);
        h8_fma(a1, v1, w1);
        h8_fma(a0, v2, w2);
        h8_fma(a1, v3, w3);
    }
    if (e + 1 < end) {
        int   s0 = g_csrc[e],  s1 = g_csrc[e + 1];
        float w0 = g_cnorm[e], w1 = g_cnorm[e + 1];
        uint4 v0 = __ldg((const uint4*)(t + (size_t)s0 * D) + lane);
        uint4 v1 = __ldg((const uint4*)(t + (size_t)s1 * D) + lane);
        h8_fma(a0, v0, w0);
        h8_fma(a1, v1, w1);
        e += 2;
    }
    if (e < end) {
        uint4 v0 = __ldg((const uint4*)(t + (size_t)g_csrc[e] * D) + lane);
        h8_fma(a0, v0, g_cnorm[e]);
    }

    float r[8];
    #pragma unroll
    for (int j = 0; j < 8; j++) {
        r[j] = a0[j] + a1[j];
        if (RELU) r[j] = fmaxf(r[j], 0.f);
    }
    if (EMIT_H) {
        uint4 o;
        *(__half2*)&o.x       = __floats2half2_rn(r[0], r[1]);
        *((__half2*)&o.x + 1) = __floats2half2_rn(r[2], r[3]);
        *(__half2*)&o.z       = __floats2half2_rn(r[4], r[5]);
        *((__half2*)&o.z + 1) = __floats2half2_rn(r[6], r[7]);
        *((uint4*)(outh + (size_t)node * D + lane * 8)) = o;
    } else {
        float4* po = (float4*)(outf + (size_t)node * D + lane * 8);
        po[0] = make_float4(r[0], r[1], r[2], r[3]);
        po[1] = make_float4(r[4], r[5], r[6], r[7]);
    }
}

// ---------------------------------------------------------------------------
// Launch
// ---------------------------------------------------------------------------
extern "C" void kernel_launch(void* const* d_in, const int* in_sizes, int n_in,
                              void* d_out, int out_size)
{
    const float* x  = (const float*)d_in[0];
    const int*   ei = (const int*)  d_in[1];
    const float* ew = (const float*)d_in[2];
    const float* W0 = (const float*)d_in[3];
    const float* b0 = (const float*)d_in[4];
    const float* W1 = (const float*)d_in[5];
    const float* b1 = (const float*)d_in[6];
    const float* W2 = (const float*)d_in[7];
    const float* b2 = (const float*)d_in[8];
    float* out = (float*)d_out;

    const int* src = ei;
    const int* dst = ei + EE;

    __half *x16, *xagg, *t16a, *t16b, *w0h, *w1h, *w2h;
    cudaGetSymbolAddress((void**)&x16,  g_x16);
    cudaGetSymbolAddress((void**)&xagg, g_xagg);
    cudaGetSymbolAddress((void**)&t16a, g_t16a);
    cudaGetSymbolAddress((void**)&t16b, g_t16b);
    cudaGetSymbolAddress((void**)&w0h, g_w0h);
    cudaGetSymbolAddress((void**)&w1h, g_w1h);
    cudaGetSymbolAddress((void**)&w2h, g_w2h);

    const int TB = 256;
    const int gN = (NN + TB - 1) / TB;
    const int gE2 = (EE / 2 + TB - 1) / TB;

    // ---- normalization + coalesced CSR build ----
    k_init<<<gN, TB>>>();
    k_deg_count<<<gE2, TB>>>(dst, ew);
    k_scan_fused<<<NBLK, 256>>>();
    k_fill<<<gE2, TB>>>(src, dst, ew);

    // ---- operand prep: x -> fp16 + weight transposes (single launch) ----
    k_prep<<<(NN * F_IN / 4 + 255) / 256, 256>>>(x, x16, W0, W1, W2);

    const int gridM = (NN + 127) / 128;   // 782

    // ---- Layer 0:  h0 = relu(agg(x) @ W0 + b0)   [fp16 end-to-end]
    agg_h<F_IN, false, true, false><<<(NN + 15) / 16, 256>>>(
        x16, xagg, nullptr, nullptr, NN);
    gemm_h<1><<<dim3(HID / 64, gridM), 256>>>(NN, F_IN, xagg, w0h, t16a, b0, HID);

    // ---- Layer 1:  h1 = relu(agg(h0 @ W1) + b1)
    gemm_h<0><<<dim3(HID / 64, gridM), 256>>>(NN, HID, t16a, w1h, t16b, nullptr, HID);
    agg_h<HID, true, true, true><<<(NN + 7) / 8, 256>>>(
        t16b, t16a, nullptr, b1, NN);

    // ---- Layer 2:  out = agg(h1 @ W2) + b2   [fp32 out]
    gemm_h<0><<<dim3(NC / 64, gridM), 256>>>(NN, HID, t16a, w2h, t16b, nullptr, NC);
    agg_h<NC, false, false, true><<<(NN + 31) / 32, 256>>>(
        t16b, nullptr, out, b2, NN);
}

// round 17
// speedup vs baseline: 1.0151x; 1.0151x over previous
#include <cuda_runtime.h>
#include <cuda_bf16.h>
#include <cuda_fp16.h>
#include <cstdint>
#include <math.h>

// Problem constants (fixed by the dataset)
#define NN   100000
#define EE   1600000
#define F_IN 128
#define HID  256
#define NC   64
#define NBLK ((NN + 255) / 256)   // 391

// ---------------------------------------------------------------------------
// Scratch (static __device__ arrays — no allocation allowed)
// ---------------------------------------------------------------------------
__device__ int2  g_dw[NN];          // .x = deg (float bits), .y = count
__device__ float g_dinv[NN];
__device__ int   g_wptr[NN];        // fill cursor
__device__ int   g_rowptr[NN + 1];
__device__ int   g_aggflag[NBLK];   // look-back scan: aggregate published?
__device__ int   g_aggval[NBLK];
__device__ __align__(16) int2  g_edge[EE];   // {src, norm(float bits)} packed
__device__ __align__(16) __half g_x16[(size_t)NN * F_IN];    // x in fp16
__device__ __align__(16) __half g_xagg[(size_t)NN * F_IN];   // agg(x) fp16
__device__ __align__(16) __half g_t16a[(size_t)NN * HID];    // fp16 ping
__device__ __align__(16) __half g_t16b[(size_t)NN * HID];    // fp16 pong
__device__ __align__(16) __half g_w0h[HID * F_IN];           // W^T fp16
__device__ __align__(16) __half g_w1h[HID * HID];
__device__ __align__(16) __half g_w2h[NC * HID];

// ---------------------------------------------------------------------------
// PTX helpers (portable sm_80+; works on generic sm_103 target)
// ---------------------------------------------------------------------------
__device__ __forceinline__ uint32_t smem_u32(const void* p) {
    uint32_t a;
    asm("{ .reg .u64 t; cvta.to.shared.u64 t, %1; cvt.u32.u64 %0, t; }"
        : "=r"(a) : "l"(p));
    return a;
}

#define LDSM4(r, addr) \
    asm volatile("ldmatrix.sync.aligned.m8n8.x4.shared.b16 {%0,%1,%2,%3}, [%4];" \
        : "=r"((r)[0]), "=r"((r)[1]), "=r"((r)[2]), "=r"((r)[3]) : "r"(addr))

#define MMA_F16(c, a, b0, b1) \
    asm volatile("mma.sync.aligned.m16n8k16.row.col.f32.f16.f16.f32 " \
        "{%0,%1,%2,%3}, {%4,%5,%6,%7}, {%8,%9}, {%0,%1,%2,%3};" \
        : "+f"((c)[0]), "+f"((c)[1]), "+f"((c)[2]), "+f"((c)[3]) \
        : "r"((a)[0]), "r"((a)[1]), "r"((a)[2]), "r"((a)[3]), "r"(b0), "r"(b1))

#define CP16(dst, src, sz) \
    asm volatile("cp.async.cg.shared.global [%0], [%1], 16, %2;" \
        :: "r"(dst), "l"(src), "r"(sz) : "memory")
#define CP_COMMIT() asm volatile("cp.async.commit_group;" ::: "memory")
template <int N>
__device__ __forceinline__ void cp_wait() {
    asm volatile("cp.async.wait_group %0;" :: "n"(N) : "memory");
}

// ---------------------------------------------------------------------------
// Preprocessing kernels
// ---------------------------------------------------------------------------
__global__ void k_init()
{
    int i = blockIdx.x * blockDim.x + threadIdx.x;
    if (i < NN) g_dw[i] = make_int2(__float_as_int(1.0f), 0);  // self-loop wt
    if (i < NBLK) g_aggflag[i] = 0;    // reset look-back flags each replay
}

// 2 edges per thread; deg+count atomics hit the same 8B pair (one sector)
__global__ void k_deg_count(const int* __restrict__ dst, const float* __restrict__ w)
{
    int i = blockIdx.x * blockDim.x + threadIdx.x;
    if (i < EE / 2) {
        int2   d2 = ((const int2*)dst)[i];
        float2 w2 = ((const float2*)w)[i];
        atomicAdd((float*)&g_dw[d2.x].x, w2.x);
        atomicAdd(&g_dw[d2.x].y, 1);
        atomicAdd((float*)&g_dw[d2.y].x, w2.y);
        atomicAdd(&g_dw[d2.y].y, 1);
    }
}

// Fused: dinv + block scan + decoupled-aggregate look-back -> rowptr.
// All NBLK=391 blocks are co-resident (256 thr, low regs): spin is safe.
__global__ void k_scan_fused()
{
    __shared__ int sh[256];
    __shared__ int sh2[256];
    const int b = blockIdx.x, t = threadIdx.x;
    const int i = b * 256 + t;
    int v = 0;
    if (i < NN) {
        int2 dw = g_dw[i];
        v = dw.y;
        g_dinv[i] = rsqrtf(__int_as_float(dw.x));
    }

    // inclusive block scan
    sh[t] = v;
    __syncthreads();
    #pragma unroll
    for (int o = 1; o < 256; o <<= 1) {
        int a = (t >= o) ? sh[t - o] : 0;
        __syncthreads();
        sh[t] += a;
        __syncthreads();
    }

    // publish this block's aggregate
    if (t == 255) {
        g_aggval[b] = sh[255];
        __threadfence();
        atomicExch(&g_aggflag[b], 1);
    }

    // look-back: cooperatively sum predecessor aggregates
    int pre = 0;
    for (int j = t; j < b; j += 256) {
        while (atomicAdd(&g_aggflag[j], 0) == 0) {}
        pre += g_aggval[j];
    }
    sh2[t] = pre;
    __syncthreads();
    #pragma unroll
    for (int o = 128; o > 0; o >>= 1) {
        if (t < o) sh2[t] += sh2[t + o];
        __syncthreads();
    }
    const int blkoff = sh2[0];

    if (i < NN) {
        int off = blkoff + sh[t] - v;   // exclusive prefix
        g_rowptr[i] = off;
        g_wptr[i]   = off;              // write cursor for fill
    }
    if (i == NN - 1) g_rowptr[NN] = EE;
}

// 2 edges per thread; ONE packed 8B store per edge (halves sector traffic)
__global__ void k_fill(const int* __restrict__ src, const int* __restrict__ dst,
                       const float* __restrict__ w)
{
    int i = blockIdx.x * blockDim.x + threadIdx.x;
    if (i < EE / 2) {
        int2   s2 = ((const int2*)src)[i];
        int2   d2 = ((const int2*)dst)[i];
        float2 w2 = ((const float2*)w)[i];
        float nm0 = g_dinv[s2.x] * w2.x * g_dinv[d2.x];
        int slot0 = atomicAdd(&g_wptr[d2.x], 1);
        g_edge[slot0] = make_int2(s2.x, __float_as_int(nm0));
        float nm1 = g_dinv[s2.y] * w2.y * g_dinv[d2.y];
        int slot1 = atomicAdd(&g_wptr[d2.y], 1);
        g_edge[slot1] = make_int2(s2.y, __float_as_int(nm1));
    }
}

// Fused operand prep: x -> fp16 (4 floats/thread) AND all three weight
// transposes (thread i also handles weight element i when in range).
#define WTOT (F_IN * HID + HID * HID + HID * NC)
__global__ void k_prep(const float* __restrict__ x, __half* __restrict__ xh,
                       const float* __restrict__ W0, const float* __restrict__ W1,
                       const float* __restrict__ W2)
{
    int i = blockIdx.x * blockDim.x + threadIdx.x;
    if (i < NN * F_IN / 4) {
        float4 v = ((const float4*)x)[i];
        ((__half2*)xh)[2 * i]     = __floats2half2_rn(v.x, v.y);
        ((__half2*)xh)[2 * i + 1] = __floats2half2_rn(v.z, v.w);
    }
    if (i < WTOT) {
        const float* W; __half* wt; int K, Ncols, j;
        if (i < F_IN * HID)                  { W = W0; wt = g_w0h; K = F_IN; Ncols = HID; j = i; }
        else if (i < F_IN * HID + HID * HID) { W = W1; wt = g_w1h; K = HID;  Ncols = HID; j = i - F_IN * HID; }
        else                                 { W = W2; wt = g_w2h; K = HID;  Ncols = NC;  j = i - F_IN * HID - HID * HID; }
        int n = j / K, k = j % K;
        wt[j] = __float2half(W[k * Ncols + n]);
    }
}

// ---------------------------------------------------------------------------
// FP16 HMMA GEMM, cp.async double-buffered (round-15 proven).
//   C[M, ldc] = A[M, KT] @ Bt[Ncols, KT]^T ; A,Bt fp16, fp32 accumulate.
//   BM=128, BN=64, BK=32, 256 threads (warps 4m x 2n, warp tile 32x32).
//   Smem: 2 stages x 12288 B (static 24 KB), 64 B rows, XOR-16B swizzle.
//   EPI=0: plain fp16 store. EPI=1: bias+relu+fp16 store.
// ---------------------------------------------------------------------------
template <int EPI>
__global__ void __launch_bounds__(256)
gemm_h(int M, int KT,
       const __half* __restrict__ A, const __half* __restrict__ B,
       __half* __restrict__ Ch, const float* __restrict__ bias, int ldc)
{
    constexpr int STG = 12288;          // A 128*64B + B 64*64B
    constexpr int OFF_A = 0, OFF_B = 8192;

    __shared__ __align__(16) char sm[2 * STG];
    const uint32_t smb = smem_u32(sm);

    const int tid  = threadIdx.x;
    const int lane = tid & 31, wid = tid >> 5;
    const int wm = wid & 3;             // 0..3  (m)
    const int wn = wid >> 2;            // 0..1  (n)
    const int rowBase = blockIdx.y * 128;
    const int colBase = blockIdx.x * 64;

    float c[2][4][4];
    #pragma unroll
    for (int mi = 0; mi < 2; mi++)
        #pragma unroll
        for (int nf = 0; nf < 4; nf++)
            #pragma unroll
            for (int j = 0; j < 4; j++) c[mi][nf][j] = 0.f;

    // ldmatrix per-lane rows + swizzle keys
    const int lane15 = lane & 15;
    int  rA[2], rB[2];
    rA[0] = wm * 32 + lane15;  rA[1] = rA[0] + 16;
    rB[0] = wn * 32 + lane15;  rB[1] = rB[0] + 16;
    const int swA0 = (rA[0] >> 1) & 3, swA1 = (rA[1] >> 1) & 3;
    const int swB0 = (rB[0] >> 1) & 3, swB1 = (rB[1] >> 1) & 3;
    const int ccB  = lane >> 4;

    const int nchunk = KT >> 5;

    // ---- tile loader (cp.async): rows of 32 fp16 = 4 x 16B chunks, swizzled
    auto ld_tiles = [&](int st, int ch) {
        const uint32_t sb = smb + st * STG;
        const int k0 = ch * 32;
        #pragma unroll
        for (int i = tid; i < 512; i += 256) {      // A: 128 rows x 4 chunks
            int row = i >> 2, cc = i & 3;
            int gr  = rowBase + row;
            uint32_t sz = (gr < M) ? 16u : 0u;
            int gra = (gr < M) ? gr : (M - 1);
            size_t go = (size_t)gra * KT + k0 + cc * 8;
            uint32_t d = row * 64 + ((cc ^ ((row >> 1) & 3)) << 4);
            CP16(sb + OFF_A + d, (const char*)(A + go), sz);
        }
        {                                            // B: 64 rows x 4 chunks
            int row = tid >> 2, cc = tid & 3;
            size_t go = (size_t)(colBase + row) * KT + k0 + cc * 8;
            uint32_t d = row * 64 + ((cc ^ ((row >> 1) & 3)) << 4);
            CP16(sb + OFF_B + d, (const char*)(B + go), 16u);
        }
    };

    ld_tiles(0, 0);
    CP_COMMIT();

    for (int ch = 0; ch < nchunk; ch++) {
        if (ch + 1 < nchunk) { ld_tiles((ch + 1) & 1, ch + 1); CP_COMMIT(); }
        if (ch + 1 < nchunk) cp_wait<1>(); else cp_wait<0>();
        __syncthreads();

        const uint32_t sb = smb + (ch & 1) * STG;
        #pragma unroll
        for (int ks = 0; ks < 2; ks++) {
            const int cc = ccB + 2 * ks;
            uint32_t a[2][4], b[2][4];
            LDSM4(a[0], sb + OFF_A + rA[0] * 64 + ((cc ^ swA0) << 4));
            LDSM4(a[1], sb + OFF_A + rA[1] * 64 + ((cc ^ swA1) << 4));
            LDSM4(b[0], sb + OFF_B + rB[0] * 64 + ((cc ^ swB0) << 4));
            LDSM4(b[1], sb + OFF_B + rB[1] * 64 + ((cc ^ swB1) << 4));
            #pragma unroll
            for (int mi = 0; mi < 2; mi++)
                #pragma unroll
                for (int nf = 0; nf < 4; nf++) {
                    const int p = nf >> 1, s = nf & 1;
                    MMA_F16(c[mi][nf], a[mi], b[p][s], b[p][s + 2]);
                }
        }
        __syncthreads();
    }

    // ---- epilogue: fp16 store (optionally bias+relu) ----
    #pragma unroll
    for (int mi = 0; mi < 2; mi++) {
        const int r0 = rowBase + wm * 32 + mi * 16 + (lane >> 2);
        #pragma unroll
        for (int nf = 0; nf < 4; nf++) {
            const int col = colBase + wn * 32 + nf * 8 + (lane & 3) * 2;
            float bx = 0.f, by = 0.f;
            if (EPI == 1) { bx = __ldg(bias + col); by = __ldg(bias + col + 1); }
            #pragma unroll
            for (int h = 0; h < 2; h++) {
                const int r = r0 + 8 * h;
                if (r >= M) continue;
                float v0 = c[mi][nf][2 * h + 0];
                float v1 = c[mi][nf][2 * h + 1];
                if (EPI == 1) {
                    v0 = fmaxf(v0 + bx, 0.f);
                    v1 = fmaxf(v1 + by, 0.f);
                }
                *(__half2*)(Ch + (size_t)r * ldc + col) = __floats2half2_rn(v0, v1);
            }
        }
    }
}

// ---------------------------------------------------------------------------
// Gather aggregation over fp16 rows (half8 = 16B per lane, 2-edge unroll —
// round-15 proven config), packed {src,norm} edge reads:
//   r = sum_e norm_e * t[src_e] + dinv[i]^2 * t[i] (+ bias) ; (relu)
//   Accumulate fp32. EMIT_H: store fp16 (GEMM input); else fp32.
// ---------------------------------------------------------------------------
__device__ __forceinline__ void h8_fma(float* acc, uint4 v, float w)
{
    float2 f0 = __half22float2(*(const __half2*)&v.x);
    float2 f1 = __half22float2(*((const __half2*)&v.x + 1));
    float2 f2 = __half22float2(*(const __half2*)&v.z);
    float2 f3 = __half22float2(*((const __half2*)&v.z + 1));
    acc[0] += w * f0.x; acc[1] += w * f0.y;
    acc[2] += w * f1.x; acc[3] += w * f1.y;
    acc[4] += w * f2.x; acc[5] += w * f2.y;
    acc[6] += w * f3.x; acc[7] += w * f3.y;
}

template <int D, bool RELU, bool EMIT_H, bool BIAS>
__global__ void agg_h(const __half* __restrict__ t,
                      __half* __restrict__ outh, float* __restrict__ outf,
                      const float* __restrict__ bias, int n)
{
    constexpr int L = D / 8;        // lanes per node (8 dims per lane)
    constexpr int G = 256 / L;      // nodes per block
    const int lane = threadIdx.x % L;
    const int sub  = threadIdx.x / L;
    const int node = blockIdx.x * G + sub;
    if (node >= n) return;

    float a0[8] = {}, a1[8] = {};
    if (BIAS) {
        float4 b0 = ((const float4*)bias)[2 * lane];
        float4 b1 = ((const float4*)bias)[2 * lane + 1];
        a0[0] = b0.x; a0[1] = b0.y; a0[2] = b0.z; a0[3] = b0.w;
        a0[4] = b1.x; a0[5] = b1.y; a0[6] = b1.z; a0[7] = b1.w;
    }
    const float di = g_dinv[node];
    {   // self loop: dinv^2 * t[node]
        uint4 sv = __ldg((const uint4*)(t + (size_t)node * D) + lane);
        h8_fma(a0, sv, di * di);
    }

    int e   = g_rowptr[node];
    int end = g_rowptr[node + 1];
    for (; e + 1 < end; e += 2) {
        int2 e0 = g_edge[e];
        int2 e1 = g_edge[e + 1];
        uint4 v0 = __ldg((const uint4*)(t + (size_t)e0.x * D) + lane);
        uint4 v1 = __ldg((const uint4*)(t + (size_t)e1.x * D) + lane);
        h8_fma(a0, v0, __int_as_float(e0.y));
        h8_fma(a1, v1, __int_as_float(e1.y));
    }
    if (e < end) {
        int2 e0 = g_edge[e];
        uint4 v0 = __ldg((const uint4*)(t + (size_t)e0.x * D) + lane);
        h8_fma(a0, v0, __int_as_float(e0.y));
    }

    float r[8];
    #pragma unroll
    for (int j = 0; j < 8; j++) {
        r[j] = a0[j] + a1[j];
        if (RELU) r[j] = fmaxf(r[j], 0.f);
    }
    if (EMIT_H) {
        uint4 o;
        *(__half2*)&o.x       = __floats2half2_rn(r[0], r[1]);
        *((__half2*)&o.x + 1) = __floats2half2_rn(r[2], r[3]);
        *(__half2*)&o.z       = __floats2half2_rn(r[4], r[5]);
        *((__half2*)&o.z + 1) = __floats2half2_rn(r[6], r[7]);
        *((uint4*)(outh + (size_t)node * D + lane * 8)) = o;
    } else {
        float4* po = (float4*)(outf + (size_t)node * D + lane * 8);
        po[0] = make_float4(r[0], r[1], r[2], r[3]);
        po[1] = make_float4(r[4], r[5], r[6], r[7]);
    }
}

// ---------------------------------------------------------------------------
// Launch
// ---------------------------------------------------------------------------
extern "C" void kernel_launch(void* const* d_in, const int* in_sizes, int n_in,
                              void* d_out, int out_size)
{
    const float* x  = (const float*)d_in[0];
    const int*   ei = (const int*)  d_in[1];
    const float* ew = (const float*)d_in[2];
    const float* W0 = (const float*)d_in[3];
    const float* b0 = (const float*)d_in[4];
    const float* W1 = (const float*)d_in[5];
    const float* b1 = (const float*)d_in[6];
    const float* W2 = (const float*)d_in[7];
    const float* b2 = (const float*)d_in[8];
    float* out = (float*)d_out;

    const int* src = ei;
    const int* dst = ei + EE;

    __half *x16, *xagg, *t16a, *t16b, *w0h, *w1h, *w2h;
    cudaGetSymbolAddress((void**)&x16,  g_x16);
    cudaGetSymbolAddress((void**)&xagg, g_xagg);
    cudaGetSymbolAddress((void**)&t16a, g_t16a);
    cudaGetSymbolAddress((void**)&t16b, g_t16b);
    cudaGetSymbolAddress((void**)&w0h, g_w0h);
    cudaGetSymbolAddress((void**)&w1h, g_w1h);
    cudaGetSymbolAddress((void**)&w2h, g_w2h);

    const int TB = 256;
    const int gN = (NN + TB - 1) / TB;
    const int gE2 = (EE / 2 + TB - 1) / TB;

    // ---- normalization + coalesced CSR build ----
    k_init<<<gN, TB>>>();
    k_deg_count<<<gE2, TB>>>(dst, ew);
    k_scan_fused<<<NBLK, 256>>>();
    k_fill<<<gE2, TB>>>(src, dst, ew);

    // ---- operand prep: x -> fp16 + weight transposes (single launch) ----
    k_prep<<<(NN * F_IN / 4 + 255) / 256, 256>>>(x, x16, W0, W1, W2);

    const int gridM = (NN + 127) / 128;   // 782

    // ---- Layer 0:  h0 = relu(agg(x) @ W0 + b0)   [fp16 end-to-end]
    agg_h<F_IN, false, true, false><<<(NN + 15) / 16, 256>>>(
        x16, xagg, nullptr, nullptr, NN);
    gemm_h<1><<<dim3(HID / 64, gridM), 256>>>(NN, F_IN, xagg, w0h, t16a, b0, HID);

    // ---- Layer 1:  h1 = relu(agg(h0 @ W1) + b1)
    gemm_h<0><<<dim3(HID / 64, gridM), 256>>>(NN, HID, t16a, w1h, t16b, nullptr, HID);
    agg_h<HID, true, true, true><<<(NN + 7) / 8, 256>>>(
        t16b, t16a, nullptr, b1, NN);

    // ---- Layer 2:  out = agg(h1 @ W2) + b2   [fp32 out]
    gemm_h<0><<<dim3(NC / 64, gridM), 256>>>(NN, HID, t16a, w2h, t16b, nullptr, NC);
    agg_h<NC, false, false, true><<<(NN + 31) / 32, 256>>>(
        t16b, nullptr, out, b2, NN);
}